// round 2
// baseline (speedup 1.0000x reference)
#include <cuda_runtime.h>
#include <cstdint>

#define BB 128
#define TT 256
#define HH 512
#define G4 2048  // 4*H

// ---------------- scratch (device globals; no allocation allowed) ----------
__device__ float g_xproj[(size_t)2 * TT * BB * G4];  // [d][t][b][4H], scan order
__device__ float g_hout0[(size_t)2 * TT * BB * HH];  // layer-0 outputs [d][t][b][H]
__device__ float g_h[2][2][BB][HH];                  // [parity][d][b][h]
__device__ float g_c[2][BB][HH];                     // [d][b][h]

// ---------------- tf32 helpers --------------------------------------------
__device__ __forceinline__ uint32_t f2tf(float f) {
    uint32_t u;
    asm("cvt.rna.tf32.f32 %0, %1;" : "=r"(u) : "f"(f));  // round-to-nearest (unbiased)
    return u;
}

__device__ __forceinline__ void mma8(float* c, const uint32_t* a, const uint32_t* b) {
    asm volatile(
        "mma.sync.aligned.m16n8k8.row.col.f32.tf32.tf32.f32 "
        "{%0,%1,%2,%3}, {%4,%5,%6,%7}, {%8,%9}, {%0,%1,%2,%3};"
        : "+f"(c[0]), "+f"(c[1]), "+f"(c[2]), "+f"(c[3])
        : "r"(a[0]), "r"(a[1]), "r"(a[2]), "r"(a[3]), "r"(b[0]), "r"(b[1]));
}

__device__ __forceinline__ float sigm(float v) { return 1.0f / (1.0f + expf(-v)); }

// ---------------- init: zero h (both parities) and c ------------------------
__global__ void init_state_kernel() {
    int idx = blockIdx.x * blockDim.x + threadIdx.x;  // float4 index
    float4 z = make_float4(0.f, 0.f, 0.f, 0.f);
    // g_h: 2*2*128*512 = 262144 floats = 65536 float4
    if (idx < 65536) reinterpret_cast<float4*>(&g_h[0][0][0][0])[idx] = z;
    // g_c: 131072 floats = 32768 float4
    if (idx < 32768) reinterpret_cast<float4*>(&g_c[0][0][0])[idx] = z;
}

// ---------------- input-projection GEMM ------------------------------------
// g_xproj[d][t][b][n] = inp(d,t,b,:) @ Wx[LAYER,d] + b[LAYER,d]
// LAYER 0: inp = x with time flip for d=1 ; LAYER 1: inp = g_hout0 (scan order)
template <int LAYER>
__global__ void __launch_bounds__(256) xproj_kernel(const float* __restrict__ x,
                                                    const float* __restrict__ Wx_all,
                                                    const float* __restrict__ b_all) {
    const int d = blockIdx.z;
    const int n0 = blockIdx.x * 64;
    const int m0 = blockIdx.y * 64;
    const int tid = threadIdx.x;
    const int lane = tid & 31, wid = tid >> 5;
    const int wm = wid >> 1, wn = wid & 1;

    const float* Wx = Wx_all + (size_t)(LAYER * 2 + d) * HH * G4;

    __shared__ float As[64][68];
    __shared__ float Bs[64][72];

    float acc[4][4];
#pragma unroll
    for (int f = 0; f < 4; f++)
#pragma unroll
        for (int e = 0; e < 4; e++) acc[f][e] = 0.f;

    for (int k0 = 0; k0 < HH; k0 += 64) {
        __syncthreads();
#pragma unroll
        for (int r = 0; r < 4; r++) {
            int lin = r * 256 + tid;
            int row = lin >> 4;
            int kq = lin & 15;
            int rg = m0 + row;  // global scan row in [0, T*B)
            int tt = rg >> 7;
            int bb = rg & (BB - 1);
            const float* src;
            if (LAYER == 0) {
                int tsrc = d ? (TT - 1 - tt) : tt;
                src = x + ((size_t)bb * TT + tsrc) * HH + k0 + kq * 4;
            } else {
                src = g_hout0 + (((size_t)d * TT + tt) * BB + bb) * HH + k0 + kq * 4;
            }
            *(float4*)&As[row][kq * 4] = *(const float4*)src;
        }
#pragma unroll
        for (int r = 0; r < 4; r++) {
            int lin = r * 256 + tid;
            int kk = lin >> 4;
            int nq = lin & 15;
            *(float4*)&Bs[kk][nq * 4] =
                *(const float4*)&Wx[(size_t)(k0 + kk) * G4 + n0 + nq * 4];
        }
        __syncthreads();
#pragma unroll
        for (int kk = 0; kk < 64; kk += 8) {
            uint32_t af[4], bf[4][2];
            int row = wm * 16 + (lane >> 2);
            af[0] = f2tf(As[row][kk + (lane & 3)]);
            af[1] = f2tf(As[row + 8][kk + (lane & 3)]);
            af[2] = f2tf(As[row][kk + (lane & 3) + 4]);
            af[3] = f2tf(As[row + 8][kk + (lane & 3) + 4]);
#pragma unroll
            for (int f = 0; f < 4; f++) {
                int nn = wn * 32 + f * 8 + (lane >> 2);
                bf[f][0] = f2tf(Bs[kk + (lane & 3)][nn]);
                bf[f][1] = f2tf(Bs[kk + (lane & 3) + 4][nn]);
            }
#pragma unroll
            for (int f = 0; f < 4; f++) mma8(acc[f], af, bf[f]);
        }
    }
    const float* bias = b_all + (size_t)(LAYER * 2 + d) * G4;
#pragma unroll
    for (int f = 0; f < 4; f++) {
        int row = m0 + wm * 16 + (lane >> 2);
        int col = n0 + wn * 32 + f * 8 + 2 * (lane & 3);
        float b0v = bias[col], b1v = bias[col + 1];
        float* dst0 = g_xproj + ((size_t)d * TT * BB + row) * G4 + col;
        *(float2*)dst0 = make_float2(acc[f][0] + b0v, acc[f][1] + b1v);
        float* dst1 = g_xproj + ((size_t)d * TT * BB + row + 8) * G4 + col;
        *(float2*)dst1 = make_float2(acc[f][2] + b0v, acc[f][3] + b1v);
    }
}

// ---------------- one recurrent step (fused GEMM + LSTM pointwise) ---------
// gates = g_xproj[d][t] + h_prev @ Wh[LAYER,d]; update c,h; emit h.
// CTA: 64 batch rows x 16 hcols (64 packed gate cols). Grid (32, 2, 2).
template <int LAYER>
__global__ void __launch_bounds__(256) lstm_step_kernel(const float* __restrict__ Wh_all,
                                                        int t, float* __restrict__ out) {
    const int d = blockIdx.z;
    const int h0 = blockIdx.x * 16;
    const int b0 = blockIdx.y * 64;
    const int tid = threadIdx.x;
    const int lane = tid & 31, wid = tid >> 5;
    const int wm = wid >> 1, wn = wid & 1;

    const float* Wh = Wh_all + (size_t)(LAYER * 2 + d) * HH * G4;
    const float* hprev = &g_h[t & 1][d][0][0];

    __shared__ float As[64][68];
    __shared__ float Bs[64][72];

    float acc[4][4];
#pragma unroll
    for (int f = 0; f < 4; f++)
#pragma unroll
        for (int e = 0; e < 4; e++) acc[f][e] = 0.f;

    for (int k0 = 0; k0 < HH; k0 += 64) {
        __syncthreads();
#pragma unroll
        for (int r = 0; r < 4; r++) {
            int lin = r * 256 + tid;
            int row = lin >> 4;
            int kq = lin & 15;
            *(float4*)&As[row][kq * 4] =
                *(const float4*)&hprev[(size_t)(b0 + row) * HH + k0 + kq * 4];
        }
        // B packed: n = g*16 + hc_local  (4 gate strips side by side)
#pragma unroll
        for (int r = 0; r < 4; r++) {
            int lin = r * 256 + tid;
            int kk = lin >> 4;
            int nq = lin & 15;
            int g = nq >> 2;
            int hcl = (nq & 3) * 4;
            *(float4*)&Bs[kk][nq * 4] =
                *(const float4*)&Wh[(size_t)(k0 + kk) * G4 + g * HH + h0 + hcl];
        }
        __syncthreads();
#pragma unroll
        for (int kk = 0; kk < 64; kk += 8) {
            uint32_t af[4], bf[4][2];
            int row = wm * 16 + (lane >> 2);
            af[0] = f2tf(As[row][kk + (lane & 3)]);
            af[1] = f2tf(As[row + 8][kk + (lane & 3)]);
            af[2] = f2tf(As[row][kk + (lane & 3) + 4]);
            af[3] = f2tf(As[row + 8][kk + (lane & 3) + 4]);
#pragma unroll
            for (int f = 0; f < 4; f++) {
                int nn = wn * 32 + f * 8 + (lane >> 2);
                bf[f][0] = f2tf(Bs[kk + (lane & 3)][nn]);
                bf[f][1] = f2tf(Bs[kk + (lane & 3) + 4][nn]);
            }
#pragma unroll
            for (int f = 0; f < 4; f++) mma8(acc[f], af, bf[f]);
        }
    }

    // stage accumulators in SMEM (reuse As) so pointwise can gather 4 gates/elem
    __syncthreads();
#pragma unroll
    for (int f = 0; f < 4; f++) {
        int row = wm * 16 + (lane >> 2);
        int col = wn * 32 + f * 8 + 2 * (lane & 3);
        As[row][col] = acc[f][0];
        As[row][col + 1] = acc[f][1];
        As[row + 8][col] = acc[f][2];
        As[row + 8][col + 1] = acc[f][3];
    }
    __syncthreads();

    const size_t xbase = ((size_t)d * TT * BB + (size_t)t * BB + b0) * G4;
#pragma unroll
    for (int e = 0; e < 4; e++) {
        int lin = e * 256 + tid;
        int row = lin >> 4;   // 0..63
        int hc = lin & 15;    // 0..15
        const float* xp = g_xproj + xbase + (size_t)row * G4;
        float iv = As[row][hc]      + xp[0 * HH + h0 + hc];
        float fv = As[row][16 + hc] + xp[1 * HH + h0 + hc];
        float gv = As[row][32 + hc] + xp[2 * HH + h0 + hc];
        float ov = As[row][48 + hc] + xp[3 * HH + h0 + hc];
        float it = sigm(iv), ft = sigm(fv), gt = tanhf(gv), ot = sigm(ov);
        float c_new = ft * g_c[d][b0 + row][h0 + hc] + it * gt;
        g_c[d][b0 + row][h0 + hc] = c_new;
        float h_new = ot * tanhf(c_new);
        g_h[(t + 1) & 1][d][b0 + row][h0 + hc] = h_new;
        if (LAYER == 0) {
            g_hout0[(((size_t)d * TT + t) * BB + b0 + row) * HH + h0 + hc] = h_new;
        } else {
            int torig = d ? (TT - 1 - t) : t;
            out[((size_t)(b0 + row) * TT + torig) * (2 * HH) + (size_t)d * HH + h0 + hc] =
                h_new;
        }
    }
}

// ---------------- launch ----------------------------------------------------
extern "C" void kernel_launch(void* const* d_in, const int* in_sizes, int n_in,
                              void* d_out, int out_size) {
    const float* x = (const float*)d_in[0];    // [B, T, H]
    const float* Wx = (const float*)d_in[1];   // [L, 2, H, 4H]
    const float* Wh = (const float*)d_in[2];   // [L, 2, H, 4H]
    const float* b = (const float*)d_in[3];    // [L, 2, 4H]
    float* out = (float*)d_out;                // [B, T, 2H]

    dim3 gx(G4 / 64, (TT * BB) / 64, 2);
    dim3 gs(HH / 16, BB / 64, 2);

    // ---- layer 0 ----
    xproj_kernel<0><<<gx, 256>>>(x, Wx, b);
    init_state_kernel<<<256, 256>>>();
    for (int t = 0; t < TT; t++) lstm_step_kernel<0><<<gs, 256>>>(Wh, t, nullptr);

    // ---- layer 1 ----
    xproj_kernel<1><<<gx, 256>>>(x, Wx, b);
    init_state_kernel<<<256, 256>>>();
    for (int t = 0; t < TT; t++) lstm_step_kernel<1><<<gs, 256>>>(Wh, t, out);
}

// round 3
// speedup vs baseline: 1.1454x; 1.1454x over previous
#include <cuda_runtime.h>
#include <cstdint>

#define BB 128
#define TT 256
#define HH 512
#define G4 2048  // 4*H
#define NCTA 128

// ---------------- scratch (device globals; no allocation allowed) ----------
__device__ float g_xproj[(size_t)2 * TT * BB * G4];  // [d][t][b][4H], scan order
__device__ float g_hout0[(size_t)2 * TT * BB * HH];  // layer-0 outputs [d][t][b][H]
__device__ float g_h[2][2][BB][HH];                  // [parity][d][b][h]
__device__ unsigned g_bar;                           // grid barrier counter

// ---------------- tf32 helpers --------------------------------------------
__device__ __forceinline__ uint32_t f2tf(float f) {
    uint32_t u;
    asm("cvt.rna.tf32.f32 %0, %1;" : "=r"(u) : "f"(f));  // round-to-nearest (unbiased)
    return u;
}

__device__ __forceinline__ void mma8(float* c, const uint32_t* a, const uint32_t* b) {
    asm volatile(
        "mma.sync.aligned.m16n8k8.row.col.f32.tf32.tf32.f32 "
        "{%0,%1,%2,%3}, {%4,%5,%6,%7}, {%8,%9}, {%0,%1,%2,%3};"
        : "+f"(c[0]), "+f"(c[1]), "+f"(c[2]), "+f"(c[3])
        : "r"(a[0]), "r"(a[1]), "r"(a[2]), "r"(a[3]), "r"(b[0]), "r"(b[1]));
}

__device__ __forceinline__ float sigm(float v) { return 1.0f / (1.0f + expf(-v)); }

// ---------------- init: zero h (both parities) and barrier ------------------
__global__ void init_state_kernel() {
    int idx = blockIdx.x * blockDim.x + threadIdx.x;
    if (idx == 0) g_bar = 0;
    float4 z = make_float4(0.f, 0.f, 0.f, 0.f);
    if (idx < 65536) reinterpret_cast<float4*>(&g_h[0][0][0][0])[idx] = z;
}

// ---------------- input-projection GEMM (unchanged, known-good) -------------
template <int LAYER>
__global__ void __launch_bounds__(256) xproj_kernel(const float* __restrict__ x,
                                                    const float* __restrict__ Wx_all,
                                                    const float* __restrict__ b_all) {
    const int d = blockIdx.z;
    const int n0 = blockIdx.x * 64;
    const int m0 = blockIdx.y * 64;
    const int tid = threadIdx.x;
    const int lane = tid & 31, wid = tid >> 5;
    const int wm = wid >> 1, wn = wid & 1;

    const float* Wx = Wx_all + (size_t)(LAYER * 2 + d) * HH * G4;

    __shared__ float As[64][68];
    __shared__ float Bs[64][72];

    float acc[4][4];
#pragma unroll
    for (int f = 0; f < 4; f++)
#pragma unroll
        for (int e = 0; e < 4; e++) acc[f][e] = 0.f;

    for (int k0 = 0; k0 < HH; k0 += 64) {
        __syncthreads();
#pragma unroll
        for (int r = 0; r < 4; r++) {
            int lin = r * 256 + tid;
            int row = lin >> 4;
            int kq = lin & 15;
            int rg = m0 + row;
            int tt = rg >> 7;
            int bb = rg & (BB - 1);
            const float* src;
            if (LAYER == 0) {
                int tsrc = d ? (TT - 1 - tt) : tt;
                src = x + ((size_t)bb * TT + tsrc) * HH + k0 + kq * 4;
            } else {
                src = g_hout0 + (((size_t)d * TT + tt) * BB + bb) * HH + k0 + kq * 4;
            }
            *(float4*)&As[row][kq * 4] = *(const float4*)src;
        }
#pragma unroll
        for (int r = 0; r < 4; r++) {
            int lin = r * 256 + tid;
            int kk = lin >> 4;
            int nq = lin & 15;
            *(float4*)&Bs[kk][nq * 4] =
                *(const float4*)&Wx[(size_t)(k0 + kk) * G4 + n0 + nq * 4];
        }
        __syncthreads();
#pragma unroll
        for (int kk = 0; kk < 64; kk += 8) {
            uint32_t af[4], bf[4][2];
            int row = wm * 16 + (lane >> 2);
            af[0] = f2tf(As[row][kk + (lane & 3)]);
            af[1] = f2tf(As[row + 8][kk + (lane & 3)]);
            af[2] = f2tf(As[row][kk + (lane & 3) + 4]);
            af[3] = f2tf(As[row + 8][kk + (lane & 3) + 4]);
#pragma unroll
            for (int f = 0; f < 4; f++) {
                int nn = wn * 32 + f * 8 + (lane >> 2);
                bf[f][0] = f2tf(Bs[kk + (lane & 3)][nn]);
                bf[f][1] = f2tf(Bs[kk + (lane & 3) + 4][nn]);
            }
#pragma unroll
            for (int f = 0; f < 4; f++) mma8(acc[f], af, bf[f]);
        }
    }
    const float* bias = b_all + (size_t)(LAYER * 2 + d) * G4;
#pragma unroll
    for (int f = 0; f < 4; f++) {
        int row = m0 + wm * 16 + (lane >> 2);
        int col = n0 + wn * 32 + f * 8 + 2 * (lane & 3);
        float b0v = bias[col], b1v = bias[col + 1];
        float* dst0 = g_xproj + ((size_t)d * TT * BB + row) * G4 + col;
        *(float2*)dst0 = make_float2(acc[f][0] + b0v, acc[f][1] + b1v);
        float* dst1 = g_xproj + ((size_t)d * TT * BB + row + 8) * G4 + col;
        *(float2*)dst1 = make_float2(acc[f][2] + b0v, acc[f][3] + b1v);
    }
}

// ---------------- persistent recurrence kernel ------------------------------
// 128 CTAs (64/dir). CTA = (dir d, 8 h-cols => 32 packed gate cols, all 128 b).
// Wh tile [512][32] resident in SMEM as tf32 for all 256 steps.
// Per step: GEMM h_prev[128,512] @ WhS -> gates[128,32]; fused LSTM pointwise;
// c kept in registers across the whole scan; grid-wide spin barrier per step.
// SMEM: WhS 512*36 u32 | Abuf 2*128*36 u32 (Gs overlays Abuf[0])
#define SM_WORDS (512 * 36 + 2 * 128 * 36)

template <int LAYER>
__global__ void __launch_bounds__(256, 1) lstm_persist_kernel(
    const float* __restrict__ Wh_all, float* __restrict__ out) {
    extern __shared__ uint32_t smem[];
    uint32_t* WhS = smem;                    // [512][36]
    uint32_t* Ab = smem + 512 * 36;          // [2][128][36]
    float* Gs = (float*)(smem + 512 * 36);   // overlay Abuf[0], [128][36]

    const int tid = threadIdx.x;
    const int lane = tid & 31, wid = tid >> 5;
    const int wm = wid >> 1, wn = wid & 1;
    const int d = blockIdx.x >> 6;
    const int h0 = (blockIdx.x & 63) * 8;

    const float* Wh = Wh_all + (size_t)(LAYER * 2 + d) * HH * G4;

    // ---- load Wh tile once, converted to tf32, gate strips packed n=g*8+hc
    for (int lin = tid; lin < 4096; lin += 256) {
        int k = lin >> 3;
        int q = lin & 7;
        int g = q >> 1;
        int part = (q & 1) * 4;
        float4 v = *(const float4*)&Wh[(size_t)k * G4 + g * HH + h0 + part];
        uint32_t* dst = &WhS[k * 36 + g * 8 + part];
        dst[0] = f2tf(v.x);
        dst[1] = f2tf(v.y);
        dst[2] = f2tf(v.z);
        dst[3] = f2tf(v.w);
    }
    __syncthreads();

    float c_reg[4] = {0.f, 0.f, 0.f, 0.f};

    for (int t = 0; t < TT; t++) {
        const float* hprev = &g_h[t & 1][d][0][0];
        float acc[2][2][4];
#pragma unroll
        for (int mt = 0; mt < 2; mt++)
#pragma unroll
            for (int nt = 0; nt < 2; nt++)
#pragma unroll
                for (int e = 0; e < 4; e++) acc[mt][nt][e] = 0.f;

        // preload k-chunk 0 (L1 bypass: parity addrs repeat; L1 not coherent)
        float4 pre[4];
#pragma unroll
        for (int j = 0; j < 4; j++) {
            int lin = j * 256 + tid;
            int row = lin >> 3, q = lin & 7;
            pre[j] = __ldcg((const float4*)&hprev[row * HH + q * 4]);
        }
#pragma unroll
        for (int j = 0; j < 4; j++) {
            int lin = j * 256 + tid;
            int row = lin >> 3, q = lin & 7;
            uint32_t* dst = &Ab[row * 36 + q * 4];
            dst[0] = f2tf(pre[j].x);
            dst[1] = f2tf(pre[j].y);
            dst[2] = f2tf(pre[j].z);
            dst[3] = f2tf(pre[j].w);
        }
        __syncthreads();

        int buf = 0;
        for (int kc = 0; kc < 16; kc++) {
            if (kc < 15) {
#pragma unroll
                for (int j = 0; j < 4; j++) {
                    int lin = j * 256 + tid;
                    int row = lin >> 3, q = lin & 7;
                    pre[j] = __ldcg(
                        (const float4*)&hprev[row * HH + (kc + 1) * 32 + q * 4]);
                }
            }
            const uint32_t* Ac = &Ab[buf * 128 * 36];
#pragma unroll
            for (int ks = 0; ks < 4; ks++) {
                uint32_t af[2][4], bfr[2][2];
                int ak = ks * 8 + (lane & 3);
                int ar = wm * 32 + (lane >> 2);
                af[0][0] = Ac[ar * 36 + ak];
                af[0][1] = Ac[(ar + 8) * 36 + ak];
                af[0][2] = Ac[ar * 36 + ak + 4];
                af[0][3] = Ac[(ar + 8) * 36 + ak + 4];
                af[1][0] = Ac[(ar + 16) * 36 + ak];
                af[1][1] = Ac[(ar + 24) * 36 + ak];
                af[1][2] = Ac[(ar + 16) * 36 + ak + 4];
                af[1][3] = Ac[(ar + 24) * 36 + ak + 4];
                int bk = kc * 32 + ks * 8 + (lane & 3);
                int bn = wn * 16 + (lane >> 2);
                bfr[0][0] = WhS[bk * 36 + bn];
                bfr[0][1] = WhS[(bk + 4) * 36 + bn];
                bfr[1][0] = WhS[bk * 36 + bn + 8];
                bfr[1][1] = WhS[(bk + 4) * 36 + bn + 8];
                mma8(acc[0][0], af[0], bfr[0]);
                mma8(acc[0][1], af[0], bfr[1]);
                mma8(acc[1][0], af[1], bfr[0]);
                mma8(acc[1][1], af[1], bfr[1]);
            }
            if (kc < 15) {
#pragma unroll
                for (int j = 0; j < 4; j++) {
                    int lin = j * 256 + tid;
                    int row = lin >> 3, q = lin & 7;
                    uint32_t* dst = &Ab[((buf ^ 1) * 128 + row) * 36 + q * 4];
                    dst[0] = f2tf(pre[j].x);
                    dst[1] = f2tf(pre[j].y);
                    dst[2] = f2tf(pre[j].z);
                    dst[3] = f2tf(pre[j].w);
                }
            }
            __syncthreads();
            buf ^= 1;
        }

        // stage accumulators into Gs (Abuf[0] region; last chunk read Abuf[1])
#pragma unroll
        for (int mt = 0; mt < 2; mt++)
#pragma unroll
            for (int nt = 0; nt < 2; nt++) {
                int row = wm * 32 + mt * 16 + (lane >> 2);
                int col = wn * 16 + nt * 8 + 2 * (lane & 3);
                Gs[row * 36 + col] = acc[mt][nt][0];
                Gs[row * 36 + col + 1] = acc[mt][nt][1];
                Gs[(row + 8) * 36 + col] = acc[mt][nt][2];
                Gs[(row + 8) * 36 + col + 1] = acc[mt][nt][3];
            }
        __syncthreads();

        // fused pointwise; c in registers
        const size_t xbase = ((size_t)d * TT * BB + (size_t)t * BB) * G4;
        float* hnext = &g_h[(t + 1) & 1][d][0][0];
#pragma unroll
        for (int e = 0; e < 4; e++) {
            int lin = e * 256 + tid;
            int row = lin >> 3;
            int hc = lin & 7;
            const float* xp = g_xproj + xbase + (size_t)row * G4 + h0 + hc;
            float iv = Gs[row * 36 + hc] + xp[0];
            float fv = Gs[row * 36 + 8 + hc] + xp[HH];
            float gv = Gs[row * 36 + 16 + hc] + xp[2 * HH];
            float ov = Gs[row * 36 + 24 + hc] + xp[3 * HH];
            float it = sigm(iv), ft = sigm(fv), gt = tanhf(gv), ot = sigm(ov);
            float cn = ft * c_reg[e] + it * gt;
            c_reg[e] = cn;
            float hn = ot * tanhf(cn);
            __stcg(&hnext[row * HH + h0 + hc], hn);
            if (LAYER == 0) {
                g_hout0[(((size_t)d * TT + t) * BB + row) * HH + h0 + hc] = hn;
            } else {
                int torig = d ? (TT - 1 - t) : t;
                out[((size_t)row * TT + torig) * (2 * HH) + (size_t)d * HH + h0 +
                    hc] = hn;
            }
        }

        // grid-wide barrier: release h writes, then arrive + spin
        __threadfence();
        __syncthreads();
        if (tid == 0) {
            atomicAdd(&g_bar, 1u);
            unsigned target = (unsigned)NCTA * (unsigned)(t + 1);
            while (*(volatile unsigned*)&g_bar < target) {
            }
        }
        __syncthreads();
        __threadfence();
    }
}

// ---------------- launch ----------------------------------------------------
extern "C" void kernel_launch(void* const* d_in, const int* in_sizes, int n_in,
                              void* d_out, int out_size) {
    const float* x = (const float*)d_in[0];   // [B, T, H]
    const float* Wx = (const float*)d_in[1];  // [L, 2, H, 4H]
    const float* Wh = (const float*)d_in[2];  // [L, 2, H, 4H]
    const float* b = (const float*)d_in[3];   // [L, 2, 4H]
    float* out = (float*)d_out;               // [B, T, 2H]

    const int smem_bytes = SM_WORDS * 4;  // 110592
    cudaFuncSetAttribute(lstm_persist_kernel<0>,
                         cudaFuncAttributeMaxDynamicSharedMemorySize, smem_bytes);
    cudaFuncSetAttribute(lstm_persist_kernel<1>,
                         cudaFuncAttributeMaxDynamicSharedMemorySize, smem_bytes);

    dim3 gx(G4 / 64, (TT * BB) / 64, 2);

    // ---- layer 0 ----
    xproj_kernel<0><<<gx, 256>>>(x, Wx, b);
    init_state_kernel<<<256, 256>>>();
    lstm_persist_kernel<0><<<NCTA, 256, smem_bytes>>>(Wh, nullptr);

    // ---- layer 1 ----
    xproj_kernel<1><<<gx, 256>>>(x, Wx, b);
    init_state_kernel<<<256, 256>>>();
    lstm_persist_kernel<1><<<NCTA, 256, smem_bytes>>>(Wh, out);
}

// round 5
// speedup vs baseline: 1.1659x; 1.0179x over previous
#include <cuda_runtime.h>
#include <cstdint>

#define BB 128
#define TT 256
#define HH 512
#define G4 2048  // 4*H
#define NCTA 128

// ---------------- scratch (device globals; no allocation allowed) ----------
__device__ float g_xproj[(size_t)2 * TT * BB * G4];  // [d][t][b][4H], scan order
__device__ float g_hout0[(size_t)2 * TT * BB * HH];  // layer-0 outputs [d][t][b][H]
__device__ float g_h[2][2][BB][HH];                  // [parity][d][b][h], tf32-pre-rounded
__device__ unsigned g_bar;                           // grid barrier counter

// ---------------- tf32 helpers --------------------------------------------
__device__ __forceinline__ uint32_t f2tf(float f) {
    uint32_t u;
    asm("cvt.rna.tf32.f32 %0, %1;" : "=r"(u) : "f"(f));  // round-to-nearest (unbiased)
    return u;
}

__device__ __forceinline__ void mma8(float* c, const uint32_t* a, const uint32_t* b) {
    asm volatile(
        "mma.sync.aligned.m16n8k8.row.col.f32.tf32.tf32.f32 "
        "{%0,%1,%2,%3}, {%4,%5,%6,%7}, {%8,%9}, {%0,%1,%2,%3};"
        : "+f"(c[0]), "+f"(c[1]), "+f"(c[2]), "+f"(c[3])
        : "r"(a[0]), "r"(a[1]), "r"(a[2]), "r"(a[3]), "r"(b[0]), "r"(b[1]));
}

__device__ __forceinline__ float sigm(float v) { return 1.0f / (1.0f + expf(-v)); }

// ---------------- init: zero h (both parities) and barrier ------------------
__global__ void init_state_kernel() {
    int idx = blockIdx.x * blockDim.x + threadIdx.x;
    if (idx == 0) g_bar = 0;
    float4 z = make_float4(0.f, 0.f, 0.f, 0.f);
    if (idx < 65536) reinterpret_cast<float4*>(&g_h[0][0][0][0])[idx] = z;
}

// ---------------- input-projection GEMM (unchanged, known-good) -------------
template <int LAYER>
__global__ void __launch_bounds__(256) xproj_kernel(const float* __restrict__ x,
                                                    const float* __restrict__ Wx_all,
                                                    const float* __restrict__ b_all) {
    const int d = blockIdx.z;
    const int n0 = blockIdx.x * 64;
    const int m0 = blockIdx.y * 64;
    const int tid = threadIdx.x;
    const int lane = tid & 31, wid = tid >> 5;
    const int wm = wid >> 1, wn = wid & 1;

    const float* Wx = Wx_all + (size_t)(LAYER * 2 + d) * HH * G4;

    __shared__ float As[64][68];
    __shared__ float Bs[64][72];

    float acc[4][4];
#pragma unroll
    for (int f = 0; f < 4; f++)
#pragma unroll
        for (int e = 0; e < 4; e++) acc[f][e] = 0.f;

    for (int k0 = 0; k0 < HH; k0 += 64) {
        __syncthreads();
#pragma unroll
        for (int r = 0; r < 4; r++) {
            int lin = r * 256 + tid;
            int row = lin >> 4;
            int kq = lin & 15;
            int rg = m0 + row;
            int tt = rg >> 7;
            int bb = rg & (BB - 1);
            const float* src;
            if (LAYER == 0) {
                int tsrc = d ? (TT - 1 - tt) : tt;
                src = x + ((size_t)bb * TT + tsrc) * HH + k0 + kq * 4;
            } else {
                src = g_hout0 + (((size_t)d * TT + tt) * BB + bb) * HH + k0 + kq * 4;
            }
            *(float4*)&As[row][kq * 4] = *(const float4*)src;
        }
#pragma unroll
        for (int r = 0; r < 4; r++) {
            int lin = r * 256 + tid;
            int kk = lin >> 4;
            int nq = lin & 15;
            *(float4*)&Bs[kk][nq * 4] =
                *(const float4*)&Wx[(size_t)(k0 + kk) * G4 + n0 + nq * 4];
        }
        __syncthreads();
#pragma unroll
        for (int kk = 0; kk < 64; kk += 8) {
            uint32_t af[4], bf[4][2];
            int row = wm * 16 + (lane >> 2);
            af[0] = f2tf(As[row][kk + (lane & 3)]);
            af[1] = f2tf(As[row + 8][kk + (lane & 3)]);
            af[2] = f2tf(As[row][kk + (lane & 3) + 4]);
            af[3] = f2tf(As[row + 8][kk + (lane & 3) + 4]);
#pragma unroll
            for (int f = 0; f < 4; f++) {
                int nn = wn * 32 + f * 8 + (lane >> 2);
                bf[f][0] = f2tf(Bs[kk + (lane & 3)][nn]);
                bf[f][1] = f2tf(Bs[kk + (lane & 3) + 4][nn]);
            }
#pragma unroll
            for (int f = 0; f < 4; f++) mma8(acc[f], af, bf[f]);
        }
    }
    const float* bias = b_all + (size_t)(LAYER * 2 + d) * G4;
#pragma unroll
    for (int f = 0; f < 4; f++) {
        int row = m0 + wm * 16 + (lane >> 2);
        int col = n0 + wn * 32 + f * 8 + 2 * (lane & 3);
        float b0v = bias[col], b1v = bias[col + 1];
        float* dst0 = g_xproj + ((size_t)d * TT * BB + row) * G4 + col;
        *(float2*)dst0 = make_float2(acc[f][0] + b0v, acc[f][1] + b1v);
        float* dst1 = g_xproj + ((size_t)d * TT * BB + row + 8) * G4 + col;
        *(float2*)dst1 = make_float2(acc[f][2] + b0v, acc[f][3] + b1v);
    }
}

// ---------------- persistent recurrence kernel ------------------------------
// 128 CTAs (64/dir). CTA = (dir d, 8 h-cols => 32 packed gate cols, all 128 b).
// Wh tile [512][32] resident in SMEM as tf32 for all 256 steps.
// h state in g_h is PRE-ROUNDED to tf32 at write time -> A path is raw bit
// moves (no cvt in the hot loop; cvt throughput was the R3 16us/step floor).
// SMEM: WhS 512*36 u32 | Abuf 2*128*36 u32 (Gs overlays Abuf[0])
#define SM_WORDS (512 * 36 + 2 * 128 * 36)

template <int LAYER>
__global__ void __launch_bounds__(256, 1) lstm_persist_kernel(
    const float* __restrict__ Wh_all, float* __restrict__ out) {
    extern __shared__ uint32_t smem[];
    uint32_t* WhS = smem;                    // [512][36]
    uint32_t* Ab = smem + 512 * 36;          // [2][128][36]
    float* Gs = (float*)(smem + 512 * 36);   // overlay Abuf[0], [128][36]

    const int tid = threadIdx.x;
    const int lane = tid & 31, wid = tid >> 5;
    const int wm = wid >> 1, wn = wid & 1;
    const int d = blockIdx.x >> 6;
    const int h0 = (blockIdx.x & 63) * 8;

    const float* Wh = Wh_all + (size_t)(LAYER * 2 + d) * HH * G4;

    // ---- load Wh tile once, converted to tf32, gate strips packed n=g*8+hc
    for (int lin = tid; lin < 4096; lin += 256) {
        int k = lin >> 3;
        int q = lin & 7;
        int g = q >> 1;
        int part = (q & 1) * 4;
        float4 v = *(const float4*)&Wh[(size_t)k * G4 + g * HH + h0 + part];
        uint32_t* dst = &WhS[k * 36 + g * 8 + part];
        dst[0] = f2tf(v.x);
        dst[1] = f2tf(v.y);
        dst[2] = f2tf(v.z);
        dst[3] = f2tf(v.w);
    }
    __syncthreads();

    float c_reg[4] = {0.f, 0.f, 0.f, 0.f};

    for (int t = 0; t < TT; t++) {
        const float* hprev = &g_h[t & 1][d][0][0];
        float acc[2][2][4];
#pragma unroll
        for (int mt = 0; mt < 2; mt++)
#pragma unroll
            for (int nt = 0; nt < 2; nt++)
#pragma unroll
                for (int e = 0; e < 4; e++) acc[mt][nt][e] = 0.f;

        // preload k-chunk 0 (L1 bypass: parity addrs repeat; L1 not coherent)
        float4 pre[4];
#pragma unroll
        for (int j = 0; j < 4; j++) {
            int lin = j * 256 + tid;
            int row = lin >> 3, q = lin & 7;
            pre[j] = __ldcg((const float4*)&hprev[row * HH + q * 4]);
        }
#pragma unroll
        for (int j = 0; j < 4; j++) {
            int lin = j * 256 + tid;
            int row = lin >> 3, q = lin & 7;
            *(float4*)&Ab[row * 36 + q * 4] = pre[j];  // raw bits: pre-rounded
        }
        __syncthreads();

        int buf = 0;
        for (int kc = 0; kc < 16; kc++) {
            if (kc < 15) {
#pragma unroll
                for (int j = 0; j < 4; j++) {
                    int lin = j * 256 + tid;
                    int row = lin >> 3, q = lin & 7;
                    pre[j] = __ldcg(
                        (const float4*)&hprev[row * HH + (kc + 1) * 32 + q * 4]);
                }
            }
            const uint32_t* Ac = &Ab[buf * 128 * 36];
#pragma unroll
            for (int ks = 0; ks < 4; ks++) {
                uint32_t af[2][4], bfr[2][2];
                int ak = ks * 8 + (lane & 3);
                int ar = wm * 32 + (lane >> 2);
                af[0][0] = Ac[ar * 36 + ak];
                af[0][1] = Ac[(ar + 8) * 36 + ak];
                af[0][2] = Ac[ar * 36 + ak + 4];
                af[0][3] = Ac[(ar + 8) * 36 + ak + 4];
                af[1][0] = Ac[(ar + 16) * 36 + ak];
                af[1][1] = Ac[(ar + 24) * 36 + ak];
                af[1][2] = Ac[(ar + 16) * 36 + ak + 4];
                af[1][3] = Ac[(ar + 24) * 36 + ak + 4];
                int bk = kc * 32 + ks * 8 + (lane & 3);
                int bn = wn * 16 + (lane >> 2);
                bfr[0][0] = WhS[bk * 36 + bn];
                bfr[0][1] = WhS[(bk + 4) * 36 + bn];
                bfr[1][0] = WhS[bk * 36 + bn + 8];
                bfr[1][1] = WhS[(bk + 4) * 36 + bn + 8];
                mma8(acc[0][0], af[0], bfr[0]);
                mma8(acc[0][1], af[0], bfr[1]);
                mma8(acc[1][0], af[1], bfr[0]);
                mma8(acc[1][1], af[1], bfr[1]);
            }
            if (kc < 15) {
#pragma unroll
                for (int j = 0; j < 4; j++) {
                    int lin = j * 256 + tid;
                    int row = lin >> 3, q = lin & 7;
                    *(float4*)&Ab[((buf ^ 1) * 128 + row) * 36 + q * 4] = pre[j];
                }
            }
            __syncthreads();
            buf ^= 1;
        }

        // stage accumulators into Gs (Abuf[0] region; last chunk read Abuf[1])
#pragma unroll
        for (int mt = 0; mt < 2; mt++)
#pragma unroll
            for (int nt = 0; nt < 2; nt++) {
                int row = wm * 32 + mt * 16 + (lane >> 2);
                int col = wn * 16 + nt * 8 + 2 * (lane & 3);
                Gs[row * 36 + col] = acc[mt][nt][0];
                Gs[row * 36 + col + 1] = acc[mt][nt][1];
                Gs[(row + 8) * 36 + col] = acc[mt][nt][2];
                Gs[(row + 8) * 36 + col + 1] = acc[mt][nt][3];
            }
        __syncthreads();

        // fused pointwise; c in registers; h stored tf32-pre-rounded
        const size_t xbase = ((size_t)d * TT * BB + (size_t)t * BB) * G4;
        float* hnext = &g_h[(t + 1) & 1][d][0][0];
#pragma unroll
        for (int e = 0; e < 4; e++) {
            int lin = e * 256 + tid;
            int row = lin >> 3;
            int hc = lin & 7;
            const float* xp = g_xproj + xbase + (size_t)row * G4 + h0 + hc;
            float iv = Gs[row * 36 + hc] + xp[0];
            float fv = Gs[row * 36 + 8 + hc] + xp[HH];
            float gv = Gs[row * 36 + 16 + hc] + xp[2 * HH];
            float ov = Gs[row * 36 + 24 + hc] + xp[3 * HH];
            float it = sigm(iv), ft = sigm(fv), gt = tanhf(gv), ot = sigm(ov);
            float cn = ft * c_reg[e] + it * gt;
            c_reg[e] = cn;
            float hn = ot * tanhf(cn);
            __stcg(&hnext[row * HH + h0 + hc], __uint_as_float(f2tf(hn)));
            if (LAYER == 0) {
                g_hout0[(((size_t)d * TT + t) * BB + row) * HH + h0 + hc] = hn;
            } else {
                int torig = d ? (TT - 1 - t) : t;
                out[((size_t)row * TT + torig) * (2 * HH) + (size_t)d * HH + h0 +
                    hc] = hn;
            }
        }

        // grid-wide barrier: release h writes, then arrive + spin
        __threadfence();
        __syncthreads();
        if (tid == 0) {
            atomicAdd(&g_bar, 1u);
            unsigned target = (unsigned)NCTA * (unsigned)(t + 1);
            while (*(volatile unsigned*)&g_bar < target) {
            }
            __threadfence();
        }
        __syncthreads();
    }
}

// ---------------- launch ----------------------------------------------------
extern "C" void kernel_launch(void* const* d_in, const int* in_sizes, int n_in,
                              void* d_out, int out_size) {
    const float* x = (const float*)d_in[0];   // [B, T, H]
    const float* Wx = (const float*)d_in[1];  // [L, 2, H, 4H]
    const float* Wh = (const float*)d_in[2];  // [L, 2, H, 4H]
    const float* b = (const float*)d_in[3];   // [L, 2, 4H]
    float* out = (float*)d_out;               // [B, T, 2H]

    const int smem_bytes = SM_WORDS * 4;  // 110592
    cudaFuncSetAttribute(lstm_persist_kernel<0>,
                         cudaFuncAttributeMaxDynamicSharedMemorySize, smem_bytes);
    cudaFuncSetAttribute(lstm_persist_kernel<1>,
                         cudaFuncAttributeMaxDynamicSharedMemorySize, smem_bytes);

    dim3 gx(G4 / 64, (TT * BB) / 64, 2);

    // ---- layer 0 ----
    xproj_kernel<0><<<gx, 256>>>(x, Wx, b);
    init_state_kernel<<<256, 256>>>();
    lstm_persist_kernel<0><<<NCTA, 256, smem_bytes>>>(Wh, nullptr);

    // ---- layer 1 ----
    xproj_kernel<1><<<gx, 256>>>(x, Wx, b);
    init_state_kernel<<<256, 256>>>();
    lstm_persist_kernel<1><<<NCTA, 256, smem_bytes>>>(Wh, out);
}